// round 13
// baseline (speedup 1.0000x reference)
#include <cuda_runtime.h>
#include <cstdint>
#include <math.h>

#define B_ 32
#define T_ 1024
#define J_ 256
#define D_ 512

// ---------------- scratch (static device globals; no allocation) ------------
__device__ float g_S[B_ * T_ * J_];       // S (f32, from gemm1)
__device__ float g_a[B_ * T_];            // ctx . w1
__device__ float g_c[B_ * J_];            // q . w2
__device__ float g_m[B_ * T_];            // rowmax over j
__device__ float g_zp[B_ * 8 * J_];       // column-sum partials (per t-block)
__device__ float g_zinv[B_ * J_];         // 1 / column sum
__device__ float g_bt[B_ * T_];           // softmax_t(rowmax)
__device__ float g_h[B_ * D_];            // sum_t bt * ctx
// bf16 fragment images (exact SMEM word layout per (block, k-tile) chunk)
__device__ uint32_t g_ap[B_ * 8 * 16 * 2048];  // gemm1 A: (b, mb, kt)
__device__ uint32_t g_bp[B_ * 2 * 16 * 2048];  // gemm1 B: (b, nb, kt)
__device__ uint32_t g_ep[B_ * 8 * 8 * 2048];   // gemm2 A (e bf16): (b, mb, kt)
__device__ uint32_t g_qp[B_ * 4 * 8 * 2048];   // gemm2 B (zinv*q): (b, nb, kt)

// ---------------- bf16 helpers ----------------------------------------------
__device__ __forceinline__ uint32_t bf2(float lo, float hi) {
    uint32_t r;
    asm("cvt.rn.bf16x2.f32 %0, %1, %2;" : "=r"(r) : "f"(hi), "f"(lo));
    return r;
}

#define MMA_BF16(c, a, bb)                                                      \
    asm("mma.sync.aligned.m16n8k16.row.col.f32.bf16.bf16.f32 "                  \
        "{%0,%1,%2,%3},{%4,%5,%6,%7},{%8,%9},{%0,%1,%2,%3};"                    \
        : "+f"((c)[0]), "+f"((c)[1]), "+f"((c)[2]), "+f"((c)[3])                \
        : "r"((a)[0]), "r"((a)[1]), "r"((a)[2]), "r"((a)[3]),                   \
          "r"((bb)[0]), "r"((bb)[1]))

// ---------------- kernel 1: a = ctx.w1, c = q.w2 ----------------------------
__global__ __launch_bounds__(256) void dotw_kernel(const float* __restrict__ ctx,
                                                   const float* __restrict__ q,
                                                   const float* __restrict__ w) {
    int gt = blockIdx.x * 256 + threadIdx.x;
    int gw = gt >> 5;
    int lane = gt & 31;
    if (gw >= B_ * T_ + B_ * J_) return;
    const float* rp;
    const float* wp;
    float* op;
    if (gw < B_ * T_) {
        rp = ctx + (size_t)gw * D_;
        wp = w;
        op = g_a + gw;
    } else {
        int r = gw - B_ * T_;
        rp = q + (size_t)r * D_;
        wp = w + D_;
        op = g_c + r;
    }
    const float4* r4 = (const float4*)rp;
    const float4* w4 = (const float4*)wp;
    float s = 0.f;
#pragma unroll
    for (int i = 0; i < 4; i++) {
        float4 x = r4[lane + i * 32];
        float4 ww = w4[lane + i * 32];
        s += x.x * ww.x + x.y * ww.y + x.z * ww.z + x.w * ww.w;
    }
#pragma unroll
    for (int off = 16; off > 0; off >>= 1) s += __shfl_xor_sync(0xffffffffu, s, off);
    if (lane == 0) *op = s;
}

// ---------------- kernel 1b: apack — ctx*w3 -> bf16 A fragments (gemm1) -----
__global__ __launch_bounds__(256) void apack_kernel(const float* __restrict__ ctx,
                                                    const float* __restrict__ w) {
    __shared__ float w3s[32];
    const int kt = blockIdx.x;
    const int mb = blockIdx.y;
    const int b = blockIdx.z;
    const int tid = threadIdx.x;
    if (tid < 8) ((float4*)w3s)[tid] = ((const float4*)(w + 2 * D_ + kt * 32))[tid];
    __syncthreads();
    const float* Ag = ctx + (size_t)b * T_ * D_ + (size_t)mb * 128 * D_ + kt * 32;
    uint32_t* chunk = g_ap + (((size_t)(b * 8 + mb) * 16) + kt) * 2048;
#pragma unroll
    for (int i = 0; i < 4; i++) {
        int f = tid + i * 256;
        int m = f >> 3, k4 = f & 7;
        int ka = k4 >> 2;
        int kl = (k4 & 3) * 4;
        int slot = (kl >> 1) & 3;
        float4 v = *(const float4*)(Ag + (size_t)m * D_ + k4 * 4);
        v.x *= w3s[k4 * 4 + 0];
        v.y *= w3s[k4 * 4 + 1];
        v.z *= w3s[k4 * 4 + 2];
        v.w *= w3s[k4 * 4 + 3];
        int r = m & 15;
        uint32_t* dst = chunk + ((ka * 8 + (m >> 4)) << 7) +
                        ((r & 7) * 4 + slot) * 4 + (r >> 3) + ((kl >= 8) ? 2 : 0);
        dst[0] = bf2(v.x, v.y);
        dst[4] = bf2(v.z, v.w);
    }
}

// ---------------- kernel 1c: bpack1 — q -> bf16 B fragments (gemm1 layout) --
__global__ __launch_bounds__(256) void bpack1_kernel(const float* __restrict__ q) {
    const int kt = blockIdx.x;   // 0..15
    const int nb = blockIdx.y;   // 0..1
    const int b = blockIdx.z;
    const int tid = threadIdx.x;
    const float* Bg = q + (size_t)b * J_ * D_ + (size_t)nb * 128 * D_ + kt * 32;
    uint32_t* chunk = g_bp + (((size_t)(b * 2 + nb) * 16) + kt) * 2048;
#pragma unroll
    for (int i = 0; i < 4; i++) {
        int f = tid + i * 256;
        int m = f >> 3, k4 = f & 7;
        int ka = k4 >> 2;
        int kl = (k4 & 3) * 4;
        int slot = (kl >> 1) & 3;
        float4 v = *(const float4*)(Bg + (size_t)m * D_ + k4 * 4);
        uint32_t* dst = chunk + ((ka * 16 + (m >> 3)) << 6) +
                        ((m & 7) * 4 + slot) * 2 + ((kl >= 8) ? 1 : 0);
        dst[0] = bf2(v.x, v.y);
        dst[2] = bf2(v.z, v.w);
    }
}

// ---------------- kernel 2: GEMM1  S = (ctx*w3) @ q^T + a + c  (bf16 mma) ---
// Mainloop: two linear fragment copies + MMA. No cvt, no scatter.
__global__ __launch_bounds__(256) void gemm1_tc() {
    __shared__ uint32_t As[2 * 8 * 128];
    __shared__ uint32_t Bs[2 * 16 * 64];

    const int tid = threadIdx.x;
    const int b = blockIdx.z;
    const int mb = blockIdx.y;
    const int nb = blockIdx.x;
    const int m0 = mb * 128;
    const int n0 = nb * 128;
    const uint4* Ap = (const uint4*)(g_ap + ((size_t)(b * 8 + mb) * 16) * 2048);
    const uint4* Bp = (const uint4*)(g_bp + ((size_t)(b * 2 + nb) * 16) * 2048);

    const int lane = tid & 31;
    const int wid = tid >> 5;
    const int warp_m = wid & 1;
    const int warp_n = wid >> 1;

    float acc[4][4][4];
#pragma unroll
    for (int i = 0; i < 4; i++)
#pragma unroll
        for (int j = 0; j < 4; j++)
#pragma unroll
            for (int k = 0; k < 4; k++) acc[i][j][k] = 0.f;

    uint4 qa0 = Ap[tid], qa1 = Ap[256 + tid];
    uint4 qb0 = Bp[tid], qb1 = Bp[256 + tid];

    const int KT = D_ / 32;
    for (int kt = 0; kt < KT; kt++) {
        *(uint4*)&As[tid * 4] = qa0;
        *(uint4*)&As[1024 + tid * 4] = qa1;
        *(uint4*)&Bs[tid * 4] = qb0;
        *(uint4*)&Bs[1024 + tid * 4] = qb1;
        __syncthreads();
        if (kt + 1 < KT) {
            qa0 = Ap[(kt + 1) * 512 + tid];
            qa1 = Ap[(kt + 1) * 512 + 256 + tid];
            qb0 = Bp[(kt + 1) * 512 + tid];
            qb1 = Bp[(kt + 1) * 512 + 256 + tid];
        }
#pragma unroll
        for (int ka = 0; ka < 2; ka++) {
            uint32_t af[4][4], bf[4][2];
#pragma unroll
            for (int ma = 0; ma < 4; ma++)
                *(uint4*)af[ma] = *(const uint4*)&As[((ka * 8 + warp_m * 4 + ma) << 7) + lane * 4];
#pragma unroll
            for (int na = 0; na < 4; na++)
                *(uint2*)bf[na] = *(const uint2*)&Bs[((ka * 16 + warp_n * 4 + na) << 6) + lane * 2];
#pragma unroll
            for (int ma = 0; ma < 4; ma++)
#pragma unroll
                for (int na = 0; na < 4; na++) MMA_BF16(acc[ma][na], af[ma], bf[na]);
        }
        __syncthreads();
    }

    // epilogue: + a[b,m] + c[b,n]
    const int g = lane >> 2;
    const int tg = lane & 3;
#pragma unroll
    for (int ma = 0; ma < 4; ma++) {
        int r0 = m0 + warp_m * 64 + ma * 16 + g;
        float a0v = g_a[b * T_ + r0];
        float a1v = g_a[b * T_ + r0 + 8];
#pragma unroll
        for (int na = 0; na < 4; na++) {
            int n = n0 + warp_n * 32 + na * 8 + tg * 2;
            float c0 = g_c[b * J_ + n];
            float c1 = g_c[b * J_ + n + 1];
            float* p0 = g_S + (size_t)(b * T_ + r0) * J_ + n;
            *(float2*)p0 = make_float2(acc[ma][na][0] + a0v + c0, acc[ma][na][1] + a0v + c1);
            *(float2*)(p0 + 8 * J_) =
                make_float2(acc[ma][na][2] + a1v + c0, acc[ma][na][3] + a1v + c1);
        }
    }
}

// ---------------- kernel 3: exp + rowmax + colsum, write bf16 A-frags -------
// Reads S (f32), writes e as gemm2 A fragment image g_ep (bf16), rowmax->g_m,
// column-sum partials->g_zp. No f32 write-back of e.
__global__ __launch_bounds__(256) void expred_kernel() {
    const int b = blockIdx.y;
    const int tb = blockIdx.x;  // 0..7  (= mb of gemm2)
    const int lane = threadIdx.x & 31;
    const int wrp = threadIdx.x >> 5;
    float* S = g_S + (size_t)b * T_ * J_;
    __shared__ float csS[8][J_];

    const int k4 = lane & 7;
    const int kt0 = lane >> 3;       // 0..3
    const int kt1 = 4 + (lane >> 3); // 4..7
    const int ka = k4 >> 2;
    const int kl = (k4 & 3) * 4;
    const int slot = (kl >> 1) & 3;
    uint32_t* base = g_ep + ((size_t)(b * 8 + tb) * 8) * 2048;

    float cs0[4] = {0.f, 0.f, 0.f, 0.f};
    float cs1[4] = {0.f, 0.f, 0.f, 0.f};
#pragma unroll 4
    for (int rr = 0; rr < 16; rr++) {
        int m = rr * 8 + wrp;        // row within 128-block
        int t = tb * 128 + m;
        float* row = S + (size_t)t * J_;
        float4 v0 = *(float4*)(row + lane * 4);
        float4 v1 = *(float4*)(row + 128 + lane * 4);
        float mx = fmaxf(fmaxf(fmaxf(v0.x, v0.y), fmaxf(v0.z, v0.w)),
                         fmaxf(fmaxf(v1.x, v1.y), fmaxf(v1.z, v1.w)));
#pragma unroll
        for (int off = 16; off > 0; off >>= 1)
            mx = fmaxf(mx, __shfl_xor_sync(0xffffffffu, mx, off));
        if (lane == 0) g_m[b * T_ + t] = mx;
        float4 e0 = make_float4(__expf(v0.x), __expf(v0.y), __expf(v0.z), __expf(v0.w));
        float4 e1 = make_float4(__expf(v1.x), __expf(v1.y), __expf(v1.z), __expf(v1.w));
        cs0[0] += e0.x; cs0[1] += e0.y; cs0[2] += e0.z; cs0[3] += e0.w;
        cs1[0] += e1.x; cs1[1] += e1.y; cs1[2] += e1.z; cs1[3] += e1.w;
        // fragment writes (gemm2 A layout)
        int r = m & 15;
        int foff = ((ka * 8 + (m >> 4)) << 7) + ((r & 7) * 4 + slot) * 4 + (r >> 3) +
                   ((kl >= 8) ? 2 : 0);
        uint32_t* d0 = base + (size_t)kt0 * 2048 + foff;
        uint32_t* d1 = base + (size_t)kt1 * 2048 + foff;
        d0[0] = bf2(e0.x, e0.y);
        d0[4] = bf2(e0.z, e0.w);
        d1[0] = bf2(e1.x, e1.y);
        d1[4] = bf2(e1.z, e1.w);
    }
#pragma unroll
    for (int i = 0; i < 4; i++) {
        csS[wrp][lane * 4 + i] = cs0[i];
        csS[wrp][128 + lane * 4 + i] = cs1[i];
    }
    __syncthreads();
    float s = 0.f;
#pragma unroll
    for (int wq = 0; wq < 8; wq++) s += csS[wq][threadIdx.x];
    g_zp[((size_t)b * 8 + tb) * J_ + threadIdx.x] = s;
}

// ---------------- kernel 3b: zinv = 1 / sum of partials ---------------------
__global__ __launch_bounds__(256) void zred_kernel() {
    const int b = blockIdx.x;
    const int j = threadIdx.x;
    float s = 0.f;
#pragma unroll
    for (int tb = 0; tb < 8; tb++) s += g_zp[((size_t)b * 8 + tb) * J_ + j];
    g_zinv[b * J_ + j] = 1.f / s;
}

// ---------------- kernel 3c: qnpack — zinv*q -> bf16 B frags (gemm2) --------
__global__ __launch_bounds__(256) void qnpack_kernel(const float* __restrict__ q) {
    const int kt = blockIdx.x;   // 0..7
    const int nb = blockIdx.y;   // 0..3
    const int b = blockIdx.z;
    const int tid = threadIdx.x;
    const float* Bg = q + (size_t)b * J_ * D_ + (size_t)kt * 32 * D_ + nb * 128;
    uint32_t* chunk = g_qp + (((size_t)(b * 4 + nb) * 8) + kt) * 2048;
#pragma unroll
    for (int i = 0; i < 2; i++) {
        int f = tid + i * 256;
        int kp = f >> 5, n4 = f & 31;
        int ka = kp >> 3;
        int pl = kp & 7;
        int slot = pl & 3;
        int regk = pl >> 2;
        float z0 = g_zinv[b * J_ + kt * 32 + kp * 2];
        float z1 = g_zinv[b * J_ + kt * 32 + kp * 2 + 1];
        float4 v0 = *(const float4*)(Bg + (size_t)(kp * 2) * D_ + n4 * 4);
        float4 v1 = *(const float4*)(Bg + (size_t)(kp * 2 + 1) * D_ + n4 * 4);
        const float* r0 = &v0.x;
        const float* r1 = &v1.x;
#pragma unroll
        for (int jj = 0; jj < 4; jj++) {
            int n = n4 * 4 + jj;
            uint32_t* dst = chunk + ((ka * 16 + (n >> 3)) << 6) +
                            ((n & 7) * 4 + slot) * 2 + regk;
            dst[0] = bf2(r0[jj] * z0, r1[jj] * z1);
        }
    }
}

// ---------------- kernel 4: b_t = softmax_t(rowmax) -------------------------
__global__ __launch_bounds__(256) void bt_kernel() {
    const int b = blockIdx.x;
    const int tid = threadIdx.x;
    const int lane = tid & 31;
    const int wid = tid >> 5;
    __shared__ float redA[8], redB[8];

    float4 v = ((const float4*)(g_m + b * T_))[tid];
    float mx = fmaxf(fmaxf(v.x, v.y), fmaxf(v.z, v.w));
#pragma unroll
    for (int off = 16; off > 0; off >>= 1) mx = fmaxf(mx, __shfl_xor_sync(0xffffffffu, mx, off));
    if (lane == 0) redA[wid] = mx;
    __syncthreads();
    float bm = redA[0];
#pragma unroll
    for (int w = 1; w < 8; w++) bm = fmaxf(bm, redA[w]);

    float e0 = __expf(v.x - bm), e1 = __expf(v.y - bm);
    float e2 = __expf(v.z - bm), e3 = __expf(v.w - bm);
    float s = e0 + e1 + e2 + e3;
#pragma unroll
    for (int off = 16; off > 0; off >>= 1) s += __shfl_xor_sync(0xffffffffu, s, off);
    if (lane == 0) redB[wid] = s;
    __syncthreads();
    float tot = 0.f;
#pragma unroll
    for (int w = 0; w < 8; w++) tot += redB[w];
    float inv = 1.f / tot;
    ((float4*)(g_bt + b * T_))[tid] = make_float4(e0 * inv, e1 * inv, e2 * inv, e3 * inv);
}

// ---------------- kernel 6: h[b,d] = sum_t bt * ctx -------------------------
__global__ __launch_bounds__(256) void h_kernel(const float* __restrict__ ctx) {
    const int b = blockIdx.y;
    const int d = blockIdx.x * 256 + threadIdx.x;
    __shared__ float bts[T_];
    for (int i = threadIdx.x; i < T_; i += 256) bts[i] = g_bt[b * T_ + i];
    __syncthreads();
    const float* cp = ctx + (size_t)b * T_ * D_ + d;
    float acc = 0.f;
#pragma unroll 4
    for (int t = 0; t < T_; t++) acc += bts[t] * cp[(size_t)t * D_];
    g_h[b * D_ + d] = acc;
}

// ---------------- kernel 7: GEMM2  U = e @ (zinv*q), fused G assembly -------
// Mainloop: two linear fragment copies + MMA.
__global__ __launch_bounds__(256) void gemm2_tc(const float* __restrict__ ctx,
                                                float* __restrict__ out) {
    __shared__ uint32_t As[2 * 8 * 128];
    __shared__ uint32_t Bs[2 * 16 * 64];

    const int tid = threadIdx.x;
    const int b = blockIdx.z;
    const int mb = blockIdx.y;
    const int nb = blockIdx.x;
    const int m0 = mb * 128;
    const uint4* Ap = (const uint4*)(g_ep + ((size_t)(b * 8 + mb) * 8) * 2048);
    const uint4* Bp = (const uint4*)(g_qp + ((size_t)(b * 4 + nb) * 8) * 2048);

    const int lane = tid & 31;
    const int wid = tid >> 5;
    const int warp_m = wid & 1;
    const int warp_n = wid >> 1;

    float acc[4][4][4];
#pragma unroll
    for (int i = 0; i < 4; i++)
#pragma unroll
        for (int j = 0; j < 4; j++)
#pragma unroll
            for (int k = 0; k < 4; k++) acc[i][j][k] = 0.f;

    uint4 qa0 = Ap[tid], qa1 = Ap[256 + tid];
    uint4 qb0 = Bp[tid], qb1 = Bp[256 + tid];

    const int KT = J_ / 32;
    for (int kt = 0; kt < KT; kt++) {
        *(uint4*)&As[tid * 4] = qa0;
        *(uint4*)&As[1024 + tid * 4] = qa1;
        *(uint4*)&Bs[tid * 4] = qb0;
        *(uint4*)&Bs[1024 + tid * 4] = qb1;
        __syncthreads();
        if (kt + 1 < KT) {
            qa0 = Ap[(kt + 1) * 512 + tid];
            qa1 = Ap[(kt + 1) * 512 + 256 + tid];
            qb0 = Bp[(kt + 1) * 512 + tid];
            qb1 = Bp[(kt + 1) * 512 + 256 + tid];
        }
#pragma unroll
        for (int ka = 0; ka < 2; ka++) {
            uint32_t af[4][4], bf[4][2];
#pragma unroll
            for (int ma = 0; ma < 4; ma++)
                *(uint4*)af[ma] = *(const uint4*)&As[((ka * 8 + warp_m * 4 + ma) << 7) + lane * 4];
#pragma unroll
            for (int na = 0; na < 4; na++)
                *(uint2*)bf[na] = *(const uint2*)&Bs[((ka * 16 + warp_n * 4 + na) << 6) + lane * 2];
#pragma unroll
            for (int ma = 0; ma < 4; ma++)
#pragma unroll
                for (int na = 0; na < 4; na++) MMA_BF16(acc[ma][na], af[ma], bf[na]);
        }
        __syncthreads();
    }

    // epilogue: G = [ctx | U | ctx*U | ctx*h]
    const int n0 = nb * 128;
    const int g = lane >> 2;
    const int tg = lane & 3;
#pragma unroll
    for (int ma = 0; ma < 4; ma++) {
        int r0 = m0 + warp_m * 64 + ma * 16 + g;
#pragma unroll
        for (int rr = 0; rr < 2; rr++) {
            int m = r0 + rr * 8;
            const float* crow = ctx + ((size_t)(b * T_ + m)) * D_;
            float* orow = out + ((size_t)(b * T_ + m)) * (4 * D_);
#pragma unroll
            for (int na = 0; na < 4; na++) {
                int n = n0 + warp_n * 32 + na * 8 + tg * 2;
                float2 cv = *(const float2*)(crow + n);
                float2 hv = *(const float2*)(g_h + b * D_ + n);
                float u0 = acc[ma][na][rr * 2 + 0];
                float u1 = acc[ma][na][rr * 2 + 1];
                *(float2*)(orow + n) = cv;
                *(float2*)(orow + D_ + n) = make_float2(u0, u1);
                *(float2*)(orow + 2 * D_ + n) = make_float2(cv.x * u0, cv.y * u1);
                *(float2*)(orow + 3 * D_ + n) = make_float2(cv.x * hv.x, cv.y * hv.y);
            }
        }
    }
}

// ---------------- launch -----------------------------------------------------
extern "C" void kernel_launch(void* const* d_in, const int* in_sizes, int n_in,
                              void* d_out, int out_size) {
    const float* ctx = (const float*)d_in[0];
    const float* q = (const float*)d_in[1];
    const float* w = (const float*)d_in[2];
    float* out = (float*)d_out;

    dotw_kernel<<<5120, 256>>>(ctx, q, w);
    apack_kernel<<<dim3(16, 8, 32), 256>>>(ctx, w);
    bpack1_kernel<<<dim3(16, 2, 32), 256>>>(q);
    gemm1_tc<<<dim3(2, 8, 32), 256>>>();         // 4th launch: ncu capture slot
    expred_kernel<<<dim3(8, 32), 256>>>();
    zred_kernel<<<32, 256>>>();
    bt_kernel<<<32, 256>>>();
    qnpack_kernel<<<dim3(8, 4, 32), 256>>>(q);
    h_kernel<<<dim3(2, 32), 256>>>(ctx);
    gemm2_tc<<<dim3(4, 8, 32), 256>>>(ctx, out);
}

// round 15
// speedup vs baseline: 1.0212x; 1.0212x over previous
#include <cuda_runtime.h>
#include <cstdint>
#include <math.h>

#define B_ 32
#define T_ 1024
#define J_ 256
#define D_ 512

// ---------------- scratch (static device globals; no allocation) ------------
__device__ float g_S[B_ * T_ * J_];       // S (f32, from gemm1)
__device__ float g_a[B_ * T_];            // ctx . w1
__device__ float g_c[B_ * J_];            // q . w2
__device__ float g_m[B_ * T_];            // rowmax over j
__device__ float g_zp[B_ * 8 * J_];       // column-sum partials (per t-block)
__device__ float g_zinv[B_ * J_];         // 1 / column sum
__device__ float g_bt[B_ * T_];           // softmax_t(rowmax)
__device__ float g_h[B_ * D_];            // sum_t bt * ctx
// bf16 fragment images (exact SMEM word layout per (block, k-tile) chunk)
__device__ uint32_t g_ap[B_ * 8 * 16 * 2048];  // gemm1 A: (b, mb, kt)
__device__ uint32_t g_bp[B_ * 2 * 16 * 2048];  // gemm1 B: (b, nb, kt)
__device__ uint32_t g_ep[B_ * 8 * 8 * 2048];   // gemm2 A (e bf16): (b, mb, kt)
__device__ uint32_t g_qp[B_ * 4 * 8 * 2048];   // gemm2 B (zinv*q): (b, nb, kt)

// ---------------- bf16 helpers ----------------------------------------------
__device__ __forceinline__ uint32_t bf2(float lo, float hi) {
    uint32_t r;
    asm("cvt.rn.bf16x2.f32 %0, %1, %2;" : "=r"(r) : "f"(hi), "f"(lo));
    return r;
}

#define MMA_BF16(c, a, bb)                                                      \
    asm("mma.sync.aligned.m16n8k16.row.col.f32.bf16.bf16.f32 "                  \
        "{%0,%1,%2,%3},{%4,%5,%6,%7},{%8,%9},{%0,%1,%2,%3};"                    \
        : "+f"((c)[0]), "+f"((c)[1]), "+f"((c)[2]), "+f"((c)[3])                \
        : "r"((a)[0]), "r"((a)[1]), "r"((a)[2]), "r"((a)[3]),                   \
          "r"((bb)[0]), "r"((bb)[1]))

// ---------------- kernel 1: a = ctx.w1, c = q.w2 ----------------------------
__global__ __launch_bounds__(256) void dotw_kernel(const float* __restrict__ ctx,
                                                   const float* __restrict__ q,
                                                   const float* __restrict__ w) {
    int gt = blockIdx.x * 256 + threadIdx.x;
    int gw = gt >> 5;
    int lane = gt & 31;
    if (gw >= B_ * T_ + B_ * J_) return;
    const float* rp;
    const float* wp;
    float* op;
    if (gw < B_ * T_) {
        rp = ctx + (size_t)gw * D_;
        wp = w;
        op = g_a + gw;
    } else {
        int r = gw - B_ * T_;
        rp = q + (size_t)r * D_;
        wp = w + D_;
        op = g_c + r;
    }
    const float4* r4 = (const float4*)rp;
    const float4* w4 = (const float4*)wp;
    float s = 0.f;
#pragma unroll
    for (int i = 0; i < 4; i++) {
        float4 x = r4[lane + i * 32];
        float4 ww = w4[lane + i * 32];
        s += x.x * ww.x + x.y * ww.y + x.z * ww.z + x.w * ww.w;
    }
#pragma unroll
    for (int off = 16; off > 0; off >>= 1) s += __shfl_xor_sync(0xffffffffu, s, off);
    if (lane == 0) *op = s;
}

// ---------------- kernel 1b: apack — ctx*w3 -> bf16 A fragments (gemm1) -----
__global__ __launch_bounds__(256) void apack_kernel(const float* __restrict__ ctx,
                                                    const float* __restrict__ w) {
    __shared__ float w3s[32];
    const int kt = blockIdx.x;
    const int mb = blockIdx.y;
    const int b = blockIdx.z;
    const int tid = threadIdx.x;
    if (tid < 8) ((float4*)w3s)[tid] = ((const float4*)(w + 2 * D_ + kt * 32))[tid];
    __syncthreads();
    const float* Ag = ctx + (size_t)b * T_ * D_ + (size_t)mb * 128 * D_ + kt * 32;
    uint32_t* chunk = g_ap + (((size_t)(b * 8 + mb) * 16) + kt) * 2048;
#pragma unroll
    for (int i = 0; i < 4; i++) {
        int f = tid + i * 256;
        int m = f >> 3, k4 = f & 7;
        int ka = k4 >> 2;
        int kl = (k4 & 3) * 4;
        int slot = (kl >> 1) & 3;
        float4 v = *(const float4*)(Ag + (size_t)m * D_ + k4 * 4);
        v.x *= w3s[k4 * 4 + 0];
        v.y *= w3s[k4 * 4 + 1];
        v.z *= w3s[k4 * 4 + 2];
        v.w *= w3s[k4 * 4 + 3];
        int r = m & 15;
        uint32_t* dst = chunk + ((ka * 8 + (m >> 4)) << 7) +
                        ((r & 7) * 4 + slot) * 4 + (r >> 3) + ((kl >= 8) ? 2 : 0);
        dst[0] = bf2(v.x, v.y);
        dst[4] = bf2(v.z, v.w);
    }
}

// ---------------- kernel 1c: bpack1 — q -> bf16 B fragments (gemm1 layout) --
__global__ __launch_bounds__(256) void bpack1_kernel(const float* __restrict__ q) {
    const int kt = blockIdx.x;   // 0..15
    const int nb = blockIdx.y;   // 0..1
    const int b = blockIdx.z;
    const int tid = threadIdx.x;
    const float* Bg = q + (size_t)b * J_ * D_ + (size_t)nb * 128 * D_ + kt * 32;
    uint32_t* chunk = g_bp + (((size_t)(b * 2 + nb) * 16) + kt) * 2048;
#pragma unroll
    for (int i = 0; i < 4; i++) {
        int f = tid + i * 256;
        int m = f >> 3, k4 = f & 7;
        int ka = k4 >> 2;
        int kl = (k4 & 3) * 4;
        int slot = (kl >> 1) & 3;
        float4 v = *(const float4*)(Bg + (size_t)m * D_ + k4 * 4);
        uint32_t* dst = chunk + ((ka * 16 + (m >> 3)) << 6) +
                        ((m & 7) * 4 + slot) * 2 + ((kl >= 8) ? 1 : 0);
        dst[0] = bf2(v.x, v.y);
        dst[2] = bf2(v.z, v.w);
    }
}

// ---------------- kernel 2: GEMM1  S = (ctx*w3) @ q^T + a + c  (bf16 mma) ---
// Double-buffered SMEM, ONE sync per k-tile: MMA on buf kt&1 overlaps the
// store of tile kt+1 into buf^1.
__global__ __launch_bounds__(256) void gemm1_tc() {
    __shared__ uint32_t As[2 * 2048];
    __shared__ uint32_t Bs[2 * 2048];

    const int tid = threadIdx.x;
    const int b = blockIdx.z;
    const int mb = blockIdx.y;
    const int nb = blockIdx.x;
    const int m0 = mb * 128;
    const int n0 = nb * 128;
    const uint4* Ap = (const uint4*)(g_ap + ((size_t)(b * 8 + mb) * 16) * 2048);
    const uint4* Bp = (const uint4*)(g_bp + ((size_t)(b * 2 + nb) * 16) * 2048);

    const int lane = tid & 31;
    const int wid = tid >> 5;
    const int warp_m = wid & 1;
    const int warp_n = wid >> 1;

    float acc[4][4][4];
#pragma unroll
    for (int i = 0; i < 4; i++)
#pragma unroll
        for (int j = 0; j < 4; j++)
#pragma unroll
            for (int k = 0; k < 4; k++) acc[i][j][k] = 0.f;

    // stage tile 0
    {
        uint4 a0 = Ap[tid], a1 = Ap[256 + tid];
        uint4 b0 = Bp[tid], b1 = Bp[256 + tid];
        *(uint4*)&As[tid * 4] = a0;
        *(uint4*)&As[1024 + tid * 4] = a1;
        *(uint4*)&Bs[tid * 4] = b0;
        *(uint4*)&Bs[1024 + tid * 4] = b1;
    }
    __syncthreads();

    const int KT = D_ / 32;
    for (int kt = 0; kt < KT; kt++) {
        const int buf = (kt & 1) * 2048;
        uint4 na0, na1, nb0, nb1;
        if (kt + 1 < KT) {
            na0 = Ap[(kt + 1) * 512 + tid];
            na1 = Ap[(kt + 1) * 512 + 256 + tid];
            nb0 = Bp[(kt + 1) * 512 + tid];
            nb1 = Bp[(kt + 1) * 512 + 256 + tid];
        }
#pragma unroll
        for (int ka = 0; ka < 2; ka++) {
            uint32_t af[4][4], bf[4][2];
#pragma unroll
            for (int ma = 0; ma < 4; ma++)
                *(uint4*)af[ma] =
                    *(const uint4*)&As[buf + ((ka * 8 + warp_m * 4 + ma) << 7) + lane * 4];
#pragma unroll
            for (int na = 0; na < 4; na++)
                *(uint2*)bf[na] =
                    *(const uint2*)&Bs[buf + ((ka * 16 + warp_n * 4 + na) << 6) + lane * 2];
#pragma unroll
            for (int ma = 0; ma < 4; ma++)
#pragma unroll
                for (int na = 0; na < 4; na++) MMA_BF16(acc[ma][na], af[ma], bf[na]);
        }
        if (kt + 1 < KT) {
            const int nbuf = ((kt + 1) & 1) * 2048;
            *(uint4*)&As[nbuf + tid * 4] = na0;
            *(uint4*)&As[nbuf + 1024 + tid * 4] = na1;
            *(uint4*)&Bs[nbuf + tid * 4] = nb0;
            *(uint4*)&Bs[nbuf + 1024 + tid * 4] = nb1;
        }
        __syncthreads();
    }

    // epilogue: + a[b,m] + c[b,n]
    const int g = lane >> 2;
    const int tg = lane & 3;
#pragma unroll
    for (int ma = 0; ma < 4; ma++) {
        int r0 = m0 + warp_m * 64 + ma * 16 + g;
        float a0v = g_a[b * T_ + r0];
        float a1v = g_a[b * T_ + r0 + 8];
#pragma unroll
        for (int na = 0; na < 4; na++) {
            int n = n0 + warp_n * 32 + na * 8 + tg * 2;
            float c0 = g_c[b * J_ + n];
            float c1 = g_c[b * J_ + n + 1];
            float* p0 = g_S + (size_t)(b * T_ + r0) * J_ + n;
            *(float2*)p0 = make_float2(acc[ma][na][0] + a0v + c0, acc[ma][na][1] + a0v + c1);
            *(float2*)(p0 + 8 * J_) =
                make_float2(acc[ma][na][2] + a1v + c0, acc[ma][na][3] + a1v + c1);
        }
    }
}

// ---------------- kernel 3: exp + rowmax + colsum, write bf16 A-frags -------
__global__ __launch_bounds__(256) void expred_kernel() {
    const int b = blockIdx.y;
    const int tb = blockIdx.x;  // 0..7  (= mb of gemm2)
    const int lane = threadIdx.x & 31;
    const int wrp = threadIdx.x >> 5;
    float* S = g_S + (size_t)b * T_ * J_;
    __shared__ float csS[8][J_];

    const int k4 = lane & 7;
    const int kt0 = lane >> 3;       // 0..3
    const int kt1 = 4 + (lane >> 3); // 4..7
    const int ka = k4 >> 2;
    const int kl = (k4 & 3) * 4;
    const int slot = (kl >> 1) & 3;
    uint32_t* base = g_ep + ((size_t)(b * 8 + tb) * 8) * 2048;

    float cs0[4] = {0.f, 0.f, 0.f, 0.f};
    float cs1[4] = {0.f, 0.f, 0.f, 0.f};
#pragma unroll 4
    for (int rr = 0; rr < 16; rr++) {
        int m = rr * 8 + wrp;        // row within 128-block
        int t = tb * 128 + m;
        float* row = S + (size_t)t * J_;
        float4 v0 = *(float4*)(row + lane * 4);
        float4 v1 = *(float4*)(row + 128 + lane * 4);
        float mx = fmaxf(fmaxf(fmaxf(v0.x, v0.y), fmaxf(v0.z, v0.w)),
                         fmaxf(fmaxf(v1.x, v1.y), fmaxf(v1.z, v1.w)));
#pragma unroll
        for (int off = 16; off > 0; off >>= 1)
            mx = fmaxf(mx, __shfl_xor_sync(0xffffffffu, mx, off));
        if (lane == 0) g_m[b * T_ + t] = mx;
        float4 e0 = make_float4(__expf(v0.x), __expf(v0.y), __expf(v0.z), __expf(v0.w));
        float4 e1 = make_float4(__expf(v1.x), __expf(v1.y), __expf(v1.z), __expf(v1.w));
        cs0[0] += e0.x; cs0[1] += e0.y; cs0[2] += e0.z; cs0[3] += e0.w;
        cs1[0] += e1.x; cs1[1] += e1.y; cs1[2] += e1.z; cs1[3] += e1.w;
        int r = m & 15;
        int foff = ((ka * 8 + (m >> 4)) << 7) + ((r & 7) * 4 + slot) * 4 + (r >> 3) +
                   ((kl >= 8) ? 2 : 0);
        uint32_t* d0 = base + (size_t)kt0 * 2048 + foff;
        uint32_t* d1 = base + (size_t)kt1 * 2048 + foff;
        d0[0] = bf2(e0.x, e0.y);
        d0[4] = bf2(e0.z, e0.w);
        d1[0] = bf2(e1.x, e1.y);
        d1[4] = bf2(e1.z, e1.w);
    }
#pragma unroll
    for (int i = 0; i < 4; i++) {
        csS[wrp][lane * 4 + i] = cs0[i];
        csS[wrp][128 + lane * 4 + i] = cs1[i];
    }
    __syncthreads();
    float s = 0.f;
#pragma unroll
    for (int wq = 0; wq < 8; wq++) s += csS[wq][threadIdx.x];
    g_zp[((size_t)b * 8 + tb) * J_ + threadIdx.x] = s;
}

// ---------------- kernel 3b: zinv = 1 / sum of partials ---------------------
__global__ __launch_bounds__(256) void zred_kernel() {
    const int b = blockIdx.x;
    const int j = threadIdx.x;
    float s = 0.f;
#pragma unroll
    for (int tb = 0; tb < 8; tb++) s += g_zp[((size_t)b * 8 + tb) * J_ + j];
    g_zinv[b * J_ + j] = 1.f / s;
}

// ---------------- kernel 3c: qnpack — zinv*q -> bf16 B frags (gemm2) --------
__global__ __launch_bounds__(256) void qnpack_kernel(const float* __restrict__ q) {
    const int kt = blockIdx.x;   // 0..7
    const int nb = blockIdx.y;   // 0..3
    const int b = blockIdx.z;
    const int tid = threadIdx.x;
    const float* Bg = q + (size_t)b * J_ * D_ + (size_t)kt * 32 * D_ + nb * 128;
    uint32_t* chunk = g_qp + (((size_t)(b * 4 + nb) * 8) + kt) * 2048;
#pragma unroll
    for (int i = 0; i < 2; i++) {
        int f = tid + i * 256;
        int kp = f >> 5, n4 = f & 31;
        int ka = kp >> 3;
        int pl = kp & 7;
        int slot = pl & 3;
        int regk = pl >> 2;
        float z0 = g_zinv[b * J_ + kt * 32 + kp * 2];
        float z1 = g_zinv[b * J_ + kt * 32 + kp * 2 + 1];
        float4 v0 = *(const float4*)(Bg + (size_t)(kp * 2) * D_ + n4 * 4);
        float4 v1 = *(const float4*)(Bg + (size_t)(kp * 2 + 1) * D_ + n4 * 4);
        const float* r0 = &v0.x;
        const float* r1 = &v1.x;
#pragma unroll
        for (int jj = 0; jj < 4; jj++) {
            int n = n4 * 4 + jj;
            uint32_t* dst = chunk + ((ka * 16 + (n >> 3)) << 6) +
                            ((n & 7) * 4 + slot) * 2 + regk;
            dst[0] = bf2(r0[jj] * z0, r1[jj] * z1);
        }
    }
}

// ---------------- kernel 4: b_t = softmax_t(rowmax) -------------------------
__global__ __launch_bounds__(256) void bt_kernel() {
    const int b = blockIdx.x;
    const int tid = threadIdx.x;
    const int lane = tid & 31;
    const int wid = tid >> 5;
    __shared__ float redA[8], redB[8];

    float4 v = ((const float4*)(g_m + b * T_))[tid];
    float mx = fmaxf(fmaxf(v.x, v.y), fmaxf(v.z, v.w));
#pragma unroll
    for (int off = 16; off > 0; off >>= 1) mx = fmaxf(mx, __shfl_xor_sync(0xffffffffu, mx, off));
    if (lane == 0) redA[wid] = mx;
    __syncthreads();
    float bm = redA[0];
#pragma unroll
    for (int w = 1; w < 8; w++) bm = fmaxf(bm, redA[w]);

    float e0 = __expf(v.x - bm), e1 = __expf(v.y - bm);
    float e2 = __expf(v.z - bm), e3 = __expf(v.w - bm);
    float s = e0 + e1 + e2 + e3;
#pragma unroll
    for (int off = 16; off > 0; off >>= 1) s += __shfl_xor_sync(0xffffffffu, s, off);
    if (lane == 0) redB[wid] = s;
    __syncthreads();
    float tot = 0.f;
#pragma unroll
    for (int w = 0; w < 8; w++) tot += redB[w];
    float inv = 1.f / tot;
    ((float4*)(g_bt + b * T_))[tid] = make_float4(e0 * inv, e1 * inv, e2 * inv, e3 * inv);
}

// ---------------- kernel 6: h[b,d] = sum_t bt * ctx -------------------------
__global__ __launch_bounds__(256) void h_kernel(const float* __restrict__ ctx) {
    const int b = blockIdx.y;
    const int d = blockIdx.x * 256 + threadIdx.x;
    __shared__ float bts[T_];
    for (int i = threadIdx.x; i < T_; i += 256) bts[i] = g_bt[b * T_ + i];
    __syncthreads();
    const float* cp = ctx + (size_t)b * T_ * D_ + d;
    float acc = 0.f;
#pragma unroll 4
    for (int t = 0; t < T_; t++) acc += bts[t] * cp[(size_t)t * D_];
    g_h[b * D_ + d] = acc;
}

// ---------------- kernel 7: GEMM2  U = e @ (zinv*q), fused G assembly -------
// Double-buffered SMEM, one sync per k-tile.
__global__ __launch_bounds__(256) void gemm2_tc(const float* __restrict__ ctx,
                                                float* __restrict__ out) {
    __shared__ uint32_t As[2 * 2048];
    __shared__ uint32_t Bs[2 * 2048];

    const int tid = threadIdx.x;
    const int b = blockIdx.z;
    const int mb = blockIdx.y;
    const int nb = blockIdx.x;
    const int m0 = mb * 128;
    const uint4* Ap = (const uint4*)(g_ep + ((size_t)(b * 8 + mb) * 8) * 2048);
    const uint4* Bp = (const uint4*)(g_qp + ((size_t)(b * 4 + nb) * 8) * 2048);

    const int lane = tid & 31;
    const int wid = tid >> 5;
    const int warp_m = wid & 1;
    const int warp_n = wid >> 1;

    float acc[4][4][4];
#pragma unroll
    for (int i = 0; i < 4; i++)
#pragma unroll
        for (int j = 0; j < 4; j++)
#pragma unroll
            for (int k = 0; k < 4; k++) acc[i][j][k] = 0.f;

    {
        uint4 a0 = Ap[tid], a1 = Ap[256 + tid];
        uint4 b0 = Bp[tid], b1 = Bp[256 + tid];
        *(uint4*)&As[tid * 4] = a0;
        *(uint4*)&As[1024 + tid * 4] = a1;
        *(uint4*)&Bs[tid * 4] = b0;
        *(uint4*)&Bs[1024 + tid * 4] = b1;
    }
    __syncthreads();

    const int KT = J_ / 32;
    for (int kt = 0; kt < KT; kt++) {
        const int buf = (kt & 1) * 2048;
        uint4 na0, na1, nb0, nb1;
        if (kt + 1 < KT) {
            na0 = Ap[(kt + 1) * 512 + tid];
            na1 = Ap[(kt + 1) * 512 + 256 + tid];
            nb0 = Bp[(kt + 1) * 512 + tid];
            nb1 = Bp[(kt + 1) * 512 + 256 + tid];
        }
#pragma unroll
        for (int ka = 0; ka < 2; ka++) {
            uint32_t af[4][4], bf[4][2];
#pragma unroll
            for (int ma = 0; ma < 4; ma++)
                *(uint4*)af[ma] =
                    *(const uint4*)&As[buf + ((ka * 8 + warp_m * 4 + ma) << 7) + lane * 4];
#pragma unroll
            for (int na = 0; na < 4; na++)
                *(uint2*)bf[na] =
                    *(const uint2*)&Bs[buf + ((ka * 16 + warp_n * 4 + na) << 6) + lane * 2];
#pragma unroll
            for (int ma = 0; ma < 4; ma++)
#pragma unroll
                for (int na = 0; na < 4; na++) MMA_BF16(acc[ma][na], af[ma], bf[na]);
        }
        if (kt + 1 < KT) {
            const int nbuf = ((kt + 1) & 1) * 2048;
            *(uint4*)&As[nbuf + tid * 4] = na0;
            *(uint4*)&As[nbuf + 1024 + tid * 4] = na1;
            *(uint4*)&Bs[nbuf + tid * 4] = nb0;
            *(uint4*)&Bs[nbuf + 1024 + tid * 4] = nb1;
        }
        __syncthreads();
    }

    // epilogue: G = [ctx | U | ctx*U | ctx*h]
    const int n0 = nb * 128;
    const int g = lane >> 2;
    const int tg = lane & 3;
#pragma unroll
    for (int ma = 0; ma < 4; ma++) {
        int r0 = m0 + warp_m * 64 + ma * 16 + g;
#pragma unroll
        for (int rr = 0; rr < 2; rr++) {
            int m = r0 + rr * 8;
            const float* crow = ctx + ((size_t)(b * T_ + m)) * D_;
            float* orow = out + ((size_t)(b * T_ + m)) * (4 * D_);
#pragma unroll
            for (int na = 0; na < 4; na++) {
                int n = n0 + warp_n * 32 + na * 8 + tg * 2;
                float2 cv = *(const float2*)(crow + n);
                float2 hv = *(const float2*)(g_h + b * D_ + n);
                float u0 = acc[ma][na][rr * 2 + 0];
                float u1 = acc[ma][na][rr * 2 + 1];
                *(float2*)(orow + n) = cv;
                *(float2*)(orow + D_ + n) = make_float2(u0, u1);
                *(float2*)(orow + 2 * D_ + n) = make_float2(cv.x * u0, cv.y * u1);
                *(float2*)(orow + 3 * D_ + n) = make_float2(cv.x * hv.x, cv.y * hv.y);
            }
        }
    }
}

// ---------------- launch -----------------------------------------------------
extern "C" void kernel_launch(void* const* d_in, const int* in_sizes, int n_in,
                              void* d_out, int out_size) {
    const float* ctx = (const float*)d_in[0];
    const float* q = (const float*)d_in[1];
    const float* w = (const float*)d_in[2];
    float* out = (float*)d_out;

    dotw_kernel<<<5120, 256>>>(ctx, q, w);
    apack_kernel<<<dim3(16, 8, 32), 256>>>(ctx, w);
    bpack1_kernel<<<dim3(16, 2, 32), 256>>>(q);
    gemm1_tc<<<dim3(2, 8, 32), 256>>>();         // 4th launch: ncu capture slot
    expred_kernel<<<dim3(8, 32), 256>>>();
    zred_kernel<<<32, 256>>>();
    bt_kernel<<<32, 256>>>();
    qnpack_kernel<<<dim3(8, 4, 32), 256>>>(q);
    h_kernel<<<dim3(2, 32), 256>>>(ctx);
    gemm2_tc<<<dim3(4, 8, 32), 256>>>(ctx, out);
}